// round 6
// baseline (speedup 1.0000x reference)
#include <cuda_runtime.h>
#include <math.h>
#include <stdint.h>

#define NTOK   65536
#define DM     128
#define HIDN   256
#define NN     17
#define NF     32
#define NODE_TOT 544
#define CATN   1088           // interleaved [node c | z1 c] pairs
#define OUTW   34

// Scratch (allocation-free: __device__ globals)
__device__ float g_h[(size_t)NTOK * HIDN];        // 64 MB
__device__ float g_n1[(size_t)NTOK * NODE_TOT];   // 143 MB: n1 after GAT1
__device__ float g_bt1[HIDN * DM];                // W1^T [256][128]
__device__ float g_bt2[CATN * HIDN];              // interleaved [W2;Wfold]^T [1088][256]
__device__ float g_bcat[CATN];                    // interleaved [b2;bfold]

__device__ __forceinline__ float gelu_erf(float v) {
    return 0.5f * v * (1.0f + erff(v * 0.7071067811865476f));
}
__device__ __forceinline__ uint32_t f2tf32(float x) {
    uint32_t u;
    asm("cvt.rna.tf32.f32 %0, %1;" : "=r"(u) : "f"(x));
    return u;
}
__device__ __forceinline__ uint32_t smem_u32(const void* p) {
    uint32_t a;
    asm("{ .reg .u64 t; cvta.to.shared.u64 t, %1; cvt.u32.u64 %0, t; }" : "=r"(a) : "l"(p));
    return a;
}
__device__ __forceinline__ void cp16(uint32_t dst, const void* src) {
    asm volatile("cp.async.cg.shared.global [%0], [%1], 16;" :: "r"(dst), "l"(src));
}
__device__ __forceinline__ void cp16z(uint32_t dst, const void* src, int srcbytes) {
    asm volatile("cp.async.cg.shared.global [%0], [%1], 16, %2;"
                 :: "r"(dst), "l"(src), "r"(srcbytes));
}
#define CP_COMMIT() asm volatile("cp.async.commit_group;" ::: "memory")
#define CP_WAIT(n)  asm volatile("cp.async.wait_group %0;" :: "n"(n) : "memory")

__device__ __forceinline__ void mma_tf32(float* d, const uint32_t* a, const uint32_t* b) {
    asm volatile(
        "mma.sync.aligned.m16n8k8.row.col.f32.tf32.tf32.f32 "
        "{%0,%1,%2,%3}, {%4,%5,%6,%7}, {%8,%9}, {%0,%1,%2,%3};"
        : "+f"(d[0]), "+f"(d[1]), "+f"(d[2]), "+f"(d[3])
        : "r"(a[0]), "r"(a[1]), "r"(a[2]), "r"(a[3]), "r"(b[0]), "r"(b[1]));
}

// ---------------------------------------------------------------------------
// Prep 1: W1 transpose, W2 transpose (interleaved even rows), bias copy.
// ---------------------------------------------------------------------------
__global__ void transpose_prep(const float* __restrict__ W1,
                               const float* __restrict__ W2,
                               const float* __restrict__ b2) {
    int i = blockIdx.x * blockDim.x + threadIdx.x;
    const int S1 = HIDN * DM;          // 32768
    const int S2 = NODE_TOT * HIDN;    // 139264
    if (i < S1) {
        int n = i / DM, k = i % DM;
        g_bt1[i] = W1[k * HIDN + n];
    } else if (i < S1 + S2) {
        int t = i - S1;
        int n = t / HIDN, k = t % HIDN;
        g_bt2[(size_t)(2 * n) * HIDN + k] = W2[k * NODE_TOT + n];
    } else if (i < S1 + S2 + NODE_TOT) {
        int n = i - S1 - S2;
        g_bcat[2 * n] = b2[n];
    }
}

// ---------------------------------------------------------------------------
// Prep 2: fold GAT1. Writes interleaved odd rows of g_bt2 / g_bcat.
//   Wfold[k,(i,f)] = sum_j adj1s[i][j] * sum_g W2[k,(j,g)] * Wg1[g][f]
// ---------------------------------------------------------------------------
__global__ __launch_bounds__(NODE_TOT) void fold_kernel(
    const float* __restrict__ W2, const float* __restrict__ b2,
    const float* __restrict__ Wg1, const float* __restrict__ bg1,
    const float* __restrict__ adj1)
{
    __shared__ float adjs[NN][NN];
    __shared__ float wg[NF][NF];        // wg[g][f]
    __shared__ float w2row[NODE_TOT];

    const int tid = threadIdx.x;
    const int k = blockIdx.x;

    if (tid < NN) {
        float v[NN];
        float mx = -1e30f;
#pragma unroll
        for (int j = 0; j < NN; j++) { v[j] = adj1[tid * NN + j]; mx = fmaxf(mx, v[j]); }
        float s = 0.0f;
#pragma unroll
        for (int j = 0; j < NN; j++) { v[j] = expf(v[j] - mx); s += v[j]; }
        const float inv = 1.0f / s;
#pragma unroll
        for (int j = 0; j < NN; j++) adjs[tid][j] = v[j] * inv;
    }
    for (int idx = tid; idx < NF * NF; idx += NODE_TOT)
        wg[idx / NF][idx % NF] = Wg1[idx];
    w2row[tid] = W2[k * NODE_TOT + tid];
    __syncthreads();

    const int i = tid >> 5, f = tid & 31;
    float acc = 0.0f;
#pragma unroll 1
    for (int j = 0; j < NN; j++) {
        float s = 0.0f;
#pragma unroll
        for (int g = 0; g < NF; g++) s = fmaf(w2row[j * NF + g], wg[g][f], s);
        acc = fmaf(adjs[i][j], s, acc);
    }
    g_bt2[(size_t)(2 * tid + 1) * HIDN + k] = acc;

    if (k == 0) {
        float accb = 0.0f;
#pragma unroll 1
        for (int j = 0; j < NN; j++) {
            float s = 0.0f;
#pragma unroll
            for (int g = 0; g < NF; g++) s = fmaf(b2[j * NF + g], wg[g][f], s);
            accb = fmaf(adjs[i][j], s, accb);
        }
        g_bcat[2 * tid + 1] = accb + bg1[f];
    }
}

// ---------------------------------------------------------------------------
// tf32 mma.sync GEMM with cp.async double-buffering.
// BM=128, BN=128, BK=32; 8 warps 2x4; warp tile 64x32 as 4x4 m16n8k8.
// Smem tiles raw fp32, pad-36 rows; cvt->tf32 at fragment load.
// mode 1: C[row][col] = gelu(acc + bias)            (width Nfull)
// mode 2: interleaved pairs -> Cn1[row][c/2] = gelu(odd) + even  (width Nfull/2)
// ---------------------------------------------------------------------------
#define STAGE_F  (128 * 36)

__global__ __launch_bounds__(256, 2) void gemm_mma(
    const float* __restrict__ A, const float* __restrict__ Bt,
    const float* __restrict__ bias, float* __restrict__ C,
    int K, int Nfull, int mode)
{
    extern __shared__ __align__(16) float sm[];
    float* As = sm;                    // 2 stages
    float* Bs = sm + 2 * STAGE_F;      // 2 stages
    const uint32_t a_base = smem_u32(As);
    const uint32_t b_base = smem_u32(Bs);

    const int tid  = threadIdx.x;
    const int lane = tid & 31;
    const int wid  = tid >> 5;
    const int wm   = wid >> 2;
    const int wn   = wid & 3;
    const int group = lane >> 2;
    const int tg    = lane & 3;

    const int m0 = blockIdx.y * 128;
    const int n0 = blockIdx.x * 128;
    const int NC = min(128, Nfull - n0);

    float acc[4][4][4];
#pragma unroll
    for (int mt = 0; mt < 4; mt++)
#pragma unroll
        for (int nt = 0; nt < 4; nt++)
#pragma unroll
            for (int r = 0; r < 4; r++) acc[mt][nt][r] = 0.0f;

    const int row_f = tid >> 3;        // 0..31? no: tid/8 -> 0..31 (idx>>3 with it)
    const int ktiles = K >> 5;

    // tile issue helper (macro-ish lambda)
    auto issue = [&](int kt, int stage) {
        const int kb = kt * 32;
        const uint32_t a_s = a_base + stage * STAGE_F * 4;
        const uint32_t b_s = b_base + stage * STAGE_F * 4;
#pragma unroll
        for (int it = 0; it < 4; it++) {
            int idx = tid + it * 256;
            int row = idx >> 3, q = idx & 7;
            cp16(a_s + (row * 36 + q * 4) * 4,
                 A + (size_t)(m0 + row) * K + kb + q * 4);
        }
#pragma unroll
        for (int it = 0; it < 4; it++) {
            int idx = tid + it * 256;
            int row = idx >> 3, q = idx & 7;
            const float* src = Bt + (size_t)(n0 + min(row, NC - 1)) * K + kb + q * 4;
            cp16z(b_s + (row * 36 + q * 4) * 4, src, row < NC ? 16 : 0);
        }
        CP_COMMIT();
    };

    issue(0, 0);

    for (int kt = 0; kt < ktiles; kt++) {
        const int stage = kt & 1;
        if (kt + 1 < ktiles) {
            issue(kt + 1, stage ^ 1);
            CP_WAIT(1);
        } else {
            CP_WAIT(0);
        }
        __syncthreads();

        const float* Ast = As + stage * STAGE_F;
        const float* Bst = Bs + stage * STAGE_F;

#pragma unroll
        for (int ks = 0; ks < 4; ks++) {
            const int kk = ks * 8;
            uint32_t a[4][4], b[4][2];
#pragma unroll
            for (int mt = 0; mt < 4; mt++) {
                const int r = wm * 64 + mt * 16 + group;
                a[mt][0] = f2tf32(Ast[r * 36 + kk + tg]);
                a[mt][1] = f2tf32(Ast[(r + 8) * 36 + kk + tg]);
                a[mt][2] = f2tf32(Ast[r * 36 + kk + tg + 4]);
                a[mt][3] = f2tf32(Ast[(r + 8) * 36 + kk + tg + 4]);
            }
#pragma unroll
            for (int nt = 0; nt < 4; nt++) {
                const int c = wn * 32 + nt * 8 + group;
                b[nt][0] = f2tf32(Bst[c * 36 + kk + tg]);
                b[nt][1] = f2tf32(Bst[c * 36 + kk + tg + 4]);
            }
#pragma unroll
            for (int mt = 0; mt < 4; mt++)
#pragma unroll
                for (int nt = 0; nt < 4; nt++)
                    mma_tf32(acc[mt][nt], a[mt], b[nt]);
        }
        __syncthreads();
    }

    // epilogue
    const int outw = (mode == 2) ? (Nfull >> 1) : Nfull;
#pragma unroll
    for (int mt = 0; mt < 4; mt++) {
        const int row = m0 + wm * 64 + mt * 16 + group;
#pragma unroll
        for (int nt = 0; nt < 4; nt++) {
            const int col = n0 + wn * 32 + nt * 8 + tg * 2;
            if (col < Nfull) {
                const float bz0 = bias[col], bz1 = bias[col + 1];
                float v0 = acc[mt][nt][0] + bz0;
                float v1 = acc[mt][nt][1] + bz1;
                float v2 = acc[mt][nt][2] + bz0;
                float v3 = acc[mt][nt][3] + bz1;
                if (mode == 1) {
                    v0 = gelu_erf(v0); v1 = gelu_erf(v1);
                    v2 = gelu_erf(v2); v3 = gelu_erf(v3);
                    *reinterpret_cast<float2*>(&C[(size_t)row * outw + col]) =
                        make_float2(v0, v1);
                    *reinterpret_cast<float2*>(&C[(size_t)(row + 8) * outw + col]) =
                        make_float2(v2, v3);
                } else {
                    // interleaved: even = nodes, odd = z1 -> n1 = gelu(z1)+nodes
                    C[(size_t)row * outw + (col >> 1)]       = gelu_erf(v1) + v0;
                    C[(size_t)(row + 8) * outw + (col >> 1)] = gelu_erf(v3) + v2;
                }
            }
        }
    }
}

// ---------------------------------------------------------------------------
// GAT2 + coord. One warp per token, lane = feature.
// ---------------------------------------------------------------------------
__global__ __launch_bounds__(256) void gat2_kernel(
    const float* __restrict__ n1,
    const float* __restrict__ adj2, const float* __restrict__ Wg2, const float* __restrict__ bg2,
    const float* __restrict__ Wc,  const float* __restrict__ bc,
    float* __restrict__ out, int ntok)
{
    __shared__ float a2s[NN][NN];

    const int tid = threadIdx.x;

    if (tid < NN) {
        float v[NN];
        float mx = -1e30f;
#pragma unroll
        for (int j = 0; j < NN; j++) { v[j] = adj2[tid * NN + j]; mx = fmaxf(mx, v[j]); }
        float s = 0.0f;
#pragma unroll
        for (int j = 0; j < NN; j++) { v[j] = expf(v[j] - mx); s += v[j]; }
        const float inv = 1.0f / s;
#pragma unroll
        for (int j = 0; j < NN; j++) a2s[tid][j] = v[j] * inv;
    }
    __syncthreads();

    const int lane = tid & 31;
    const int warp = tid >> 5;

    float wg2[NF];
#pragma unroll
    for (int g = 0; g < NF; g++) wg2[g] = Wg2[g * NF + lane];
    const float bg2v = bg2[lane];
    const float wc0 = Wc[lane * 2 + 0];
    const float wc1 = Wc[lane * 2 + 1];
    const float bc0 = bc[0], bc1 = bc[1];

    const int gw = blockIdx.x * (blockDim.x >> 5) + warp;
    const int nwarps = gridDim.x * (blockDim.x >> 5);

    for (int t = gw; t < ntok; t += nwarps) {
        const float* np = n1 + (size_t)t * NODE_TOT;
        float n[NN];
#pragma unroll
        for (int j = 0; j < NN; j++) n[j] = np[j * NF + lane];

        float mx2[NN];
#pragma unroll
        for (int i = 0; i < NN; i++) {
            float m = 0.0f;
#pragma unroll
            for (int j = 0; j < NN; j++) m = fmaf(a2s[i][j], n[j], m);
            mx2[i] = m;
        }
#pragma unroll
        for (int i = 0; i < NN; i++) {
            float acc = bg2v;
#pragma unroll
            for (int g = 0; g < NF; g++)
                acc = fmaf(__shfl_sync(0xffffffffu, mx2[i], g), wg2[g], acc);
            n[i] = gelu_erf(acc) + n[i];
        }

#pragma unroll
        for (int i = 0; i < NN; i++) {
            float v0 = n[i] * wc0;
            float v1 = n[i] * wc1;
#pragma unroll
            for (int off = 16; off > 0; off >>= 1) {
                v0 += __shfl_xor_sync(0xffffffffu, v0, off);
                v1 += __shfl_xor_sync(0xffffffffu, v1, off);
            }
            if (lane == 0) {
                out[(size_t)t * OUTW + i * 2 + 0] = v0 + bc0;
                out[(size_t)t * OUTW + i * 2 + 1] = v1 + bc1;
            }
        }
    }
}

// ---------------------------------------------------------------------------
extern "C" void kernel_launch(void* const* d_in, const int* in_sizes, int n_in,
                              void* d_out, int out_size)
{
    const float* x    = (const float*)d_in[0];
    const float* W1   = (const float*)d_in[1];
    const float* b1   = (const float*)d_in[2];
    const float* W2   = (const float*)d_in[3];
    const float* b2   = (const float*)d_in[4];
    const float* adj1 = (const float*)d_in[5];
    const float* Wg1  = (const float*)d_in[6];
    const float* bg1  = (const float*)d_in[7];
    const float* adj2 = (const float*)d_in[8];
    const float* Wg2  = (const float*)d_in[9];
    const float* bg2  = (const float*)d_in[10];
    const float* Wc   = (const float*)d_in[11];
    const float* bc   = (const float*)d_in[12];
    float* out = (float*)d_out;

    const int M = in_sizes[0] / DM;   // 65536 tokens

    float *h_buf = nullptr, *n1_buf = nullptr, *bt1 = nullptr, *bt2 = nullptr, *bcat = nullptr;
    cudaGetSymbolAddress((void**)&h_buf, g_h);
    cudaGetSymbolAddress((void**)&n1_buf, g_n1);
    cudaGetSymbolAddress((void**)&bt1, g_bt1);
    cudaGetSymbolAddress((void**)&bt2, g_bt2);
    cudaGetSymbolAddress((void**)&bcat, g_bcat);

    const int SMEM = 4 * STAGE_F * 4;  // 73728 B
    static bool attr_set = false;
    if (!attr_set) {
        cudaFuncSetAttribute(gemm_mma, cudaFuncAttributeMaxDynamicSharedMemorySize, SMEM);
        attr_set = true;
    }

    // Prep: transposes + GAT1 fold (interleaved columns)
    const int TT = HIDN * DM + NODE_TOT * HIDN + NODE_TOT;
    transpose_prep<<<(TT + 255) / 256, 256>>>(W1, W2, b2);
    fold_kernel<<<HIDN, NODE_TOT>>>(W2, b2, Wg1, bg1, adj1);

    // h = gelu(x @ W1 + b1)
    gemm_mma<<<dim3(HIDN / 128, M / 128), 256, SMEM>>>(x, bt1, b1, h_buf, DM, HIDN, 1);

    // n1 = gelu(z1) + nodes, computed from interleaved [W2|Wfold] GEMM
    gemm_mma<<<dim3((CATN + 127) / 128, M / 128), 256, SMEM>>>(h_buf, bt2, bcat, n1_buf,
                                                               HIDN, CATN, 2);

    // GAT2 + coord
    gat2_kernel<<<2048, 256>>>(n1_buf, adj2, Wg2, bg2, Wc, bc, out, M);
}